// round 2
// baseline (speedup 1.0000x reference)
#include <cuda_runtime.h>
#include <cstdint>

// Problem dims
#define BB 8192
#define HH 1024
#define EE 8

// GEMM tile
#define BM 128
#define BN 128
#define BK 32
#define NITER (HH / BK)   // 32

// ---------------------------------------------------------------------------
// Device scratch (no allocation allowed anywhere)
// ---------------------------------------------------------------------------
__device__ int   g_cnt[EE];
__device__ int   g_tok[EE * BB];            // packed: tok | (slot << 31)
__device__ float g_wt [EE * BB];
__device__ float g_scr[2u * BB * HH];       // 64 MB: per-slot expert outputs

// ---------------------------------------------------------------------------
__device__ __forceinline__ uint32_t f2tf32(float f) {
    uint32_t r;
    asm("cvt.rna.tf32.f32 %0, %1;" : "=r"(r) : "f"(f));
    return r;
}

__device__ __forceinline__ void mma_tf32(float* c, float4 a,
                                         uint32_t b0, uint32_t b1) {
    asm volatile(
        "mma.sync.aligned.m16n8k8.row.col.f32.tf32.tf32.f32 "
        "{%0,%1,%2,%3}, {%4,%5,%6,%7}, {%8,%9}, {%0,%1,%2,%3};"
        : "+f"(c[0]), "+f"(c[1]), "+f"(c[2]), "+f"(c[3])
        : "r"(__float_as_uint(a.x)), "r"(__float_as_uint(a.y)),
          "r"(__float_as_uint(a.z)), "r"(__float_as_uint(a.w)),
          "r"(b0), "r"(b1));
}

// ---------------------------------------------------------------------------
// Kernel 0: zero routing counters
// ---------------------------------------------------------------------------
__global__ void zero_cnt_kernel() {
    if (threadIdx.x < EE) g_cnt[threadIdx.x] = 0;
}

// ---------------------------------------------------------------------------
// Kernel 1: routing — one warp per token. Exact fp32 logits, top-2 with
// first-occurrence tie-break (matches jax.lax.top_k), softmax over the 2.
// Slot bit (0 = top-1 expert, 1 = top-2 expert) packed into token index.
// ---------------------------------------------------------------------------
__global__ void __launch_bounds__(256) route_kernel(
    const float* __restrict__ x, const float* __restrict__ gw) {
    int tok = (blockIdx.x * blockDim.x + threadIdx.x) >> 5;
    int lid = threadIdx.x & 31;
    if (tok >= BB) return;

    const float* xr = x + (size_t)tok * HH;
    float acc[EE];
#pragma unroll
    for (int e = 0; e < EE; e++) acc[e] = 0.f;

    for (int i = lid; i < HH; i += 32) {
        float xv = xr[i];
        const float4* g = reinterpret_cast<const float4*>(gw + (size_t)i * EE);
        float4 g0 = g[0], g1 = g[1];
        acc[0] += xv * g0.x; acc[1] += xv * g0.y;
        acc[2] += xv * g0.z; acc[3] += xv * g0.w;
        acc[4] += xv * g1.x; acc[5] += xv * g1.y;
        acc[6] += xv * g1.z; acc[7] += xv * g1.w;
    }
#pragma unroll
    for (int off = 16; off > 0; off >>= 1)
#pragma unroll
        for (int e = 0; e < EE; e++)
            acc[e] += __shfl_xor_sync(0xffffffffu, acc[e], off);

    if (lid == 0) {
        int i0 = 0; float v0 = acc[0];
#pragma unroll
        for (int e = 1; e < EE; e++)
            if (acc[e] > v0) { v0 = acc[e]; i0 = e; }
        int i1 = -1; float v1 = -3.4e38f;
#pragma unroll
        for (int e = 0; e < EE; e++)
            if (e != i0 && acc[e] > v1) { v1 = acc[e]; i1 = e; }
        float ex1 = expf(v1 - v0);
        float inv = 1.0f / (1.0f + ex1);
        int p0 = atomicAdd(&g_cnt[i0], 1);
        g_tok[i0 * BB + p0] = tok;                    // slot 0
        g_wt [i0 * BB + p0] = inv;
        int p1 = atomicAdd(&g_cnt[i1], 1);
        g_tok[i1 * BB + p1] = tok | (int)0x80000000;  // slot 1
        g_wt [i1 * BB + p1] = ex1 * inv;
    }
}

// ---------------------------------------------------------------------------
// Kernel 2: grouped expert GEMM, mma.sync tf32 (sm_103 baseline path).
//
// Block 128x128x32, 256 threads, 8 warps in a 4x2 grid -> warp tile 32x64.
// Fragment-major smem: each (kstep, 16-row/16-col tile) stores one float4
// per lane holding exactly that lane's mma fragment, so producer STS.128
// and consumer LDS.128 are contiguous, conflict-free 512B warp accesses.
// Warps 0-3 produce A (gathered token rows, kstep = warp id);
// warps 4-7 produce B (weight tile, kstep = warp id - 4).
// Software pipeline: regs stage globals for iter k+1 during compute of k.
// Epilogue: scale by routing weight, plain STG to per-slot scratch.
// ---------------------------------------------------------------------------
__global__ void __launch_bounds__(256, 1)
moe_gemm_kernel(const float* __restrict__ x, const float* __restrict__ ew) {
    int e   = blockIdx.z;
    int cnt = g_cnt[e];
    int m0  = blockIdx.y * BM;
    if (m0 >= cnt) return;
    int rows = min(BM, cnt - m0);
    int n0   = blockIdx.x * BN;

    __shared__ float4 sA[4 * 8 * 32];   // [kstep][mtile16][lane] 16KB
    __shared__ float4 sB[4 * 8 * 32];   // [kstep][npair16][lane] 16KB
    __shared__ int    s_pack[BM];
    __shared__ float  s_w[BM];

    int tid  = threadIdx.x;
    int lane = tid & 31;
    int w    = tid >> 5;
    int wm   = w >> 1;      // 0..3 (M direction)
    int wn   = w & 1;       // 0..1 (N direction)

    if (tid < BM) {
        int idx = m0 + tid;
        if (idx < cnt) {
            s_pack[tid] = g_tok[e * BB + idx];
            s_w[tid]    = g_wt [e * BB + idx];
        } else {
            s_pack[tid] = 0;
            s_w[tid]    = 0.f;
        }
    }
    __syncthreads();

    float acc[2][8][4];
#pragma unroll
    for (int mt = 0; mt < 2; mt++)
#pragma unroll
        for (int nt = 0; nt < 8; nt++)
#pragma unroll
            for (int q = 0; q < 4; q++) acc[mt][nt][q] = 0.f;

    // ---- producer setup ----
    const bool isA = (w < 4);
    const float* gB = ew + (size_t)e * HH * HH;
    uint32_t off0[8], off1[8];
    uint32_t vmask = 0;

    if (isA) {
        int kstep = w, r = lane >> 2, kin = lane & 3;
#pragma unroll
        for (int j = 0; j < 8; j++) {
            int ma = j * 16 + r;
            int mb = ma + 8;
            int t0 = s_pack[ma] & 0x7fffffff;
            int t1 = s_pack[mb] & 0x7fffffff;
            off0[j] = (uint32_t)t0 * HH + kstep * 8 + kin;
            off1[j] = (uint32_t)t1 * HH + kstep * 8 + kin;
            if (ma < rows) vmask |= 1u << (2 * j);
            if (mb < rows) vmask |= 2u << (2 * j);
        }
    } else {
        int kstep = w - 4, kq = lane & 3, nl = lane >> 2;
#pragma unroll
        for (int j = 0; j < 8; j++) {
            off0[j] = (uint32_t)(kstep * 8 + kq) * HH + n0 + j * 16 + nl;
            off1[j] = off0[j] + 4 * HH;
        }
    }

    uint32_t st[32];

    // stage loads for one k-chunk into registers
    auto load_stage = [&](int kc) {
        if (isA) {
            const float* p = x + kc * BK;
#pragma unroll
            for (int j = 0; j < 8; j++) {
                bool va = (vmask >> (2 * j)) & 1;
                bool vb = (vmask >> (2 * j)) & 2;
                float a0 = va ? __ldg(p + off0[j])     : 0.f;
                float a1 = vb ? __ldg(p + off1[j])     : 0.f;
                float a2 = va ? __ldg(p + off0[j] + 4) : 0.f;
                float a3 = vb ? __ldg(p + off1[j] + 4) : 0.f;
                st[j * 4 + 0] = f2tf32(a0);
                st[j * 4 + 1] = f2tf32(a1);
                st[j * 4 + 2] = f2tf32(a2);
                st[j * 4 + 3] = f2tf32(a3);
            }
        } else {
            const float* p = gB + (size_t)kc * BK * HH;
#pragma unroll
            for (int j = 0; j < 8; j++) {
                float b0 = __ldg(p + off0[j]);
                float b1 = __ldg(p + off1[j]);
                float b2 = __ldg(p + off0[j] + 8);
                float b3 = __ldg(p + off1[j] + 8);
                st[j * 4 + 0] = f2tf32(b0);
                st[j * 4 + 1] = f2tf32(b1);
                st[j * 4 + 2] = f2tf32(b2);
                st[j * 4 + 3] = f2tf32(b3);
            }
        }
    };

    auto store_stage = [&]() {
        if (isA) {
#pragma unroll
            for (int j = 0; j < 8; j++)
                sA[(w * 8 + j) * 32 + lane] = make_float4(
                    __uint_as_float(st[j * 4 + 0]), __uint_as_float(st[j * 4 + 1]),
                    __uint_as_float(st[j * 4 + 2]), __uint_as_float(st[j * 4 + 3]));
        } else {
#pragma unroll
            for (int j = 0; j < 8; j++)
                sB[((w - 4) * 8 + j) * 32 + lane] = make_float4(
                    __uint_as_float(st[j * 4 + 0]), __uint_as_float(st[j * 4 + 1]),
                    __uint_as_float(st[j * 4 + 2]), __uint_as_float(st[j * 4 + 3]));
        }
    };

    load_stage(0);

    for (int kc = 0; kc < NITER; kc++) {
        __syncthreads();      // consumers of previous chunk done
        store_stage();
        __syncthreads();      // smem ready
        if (kc + 1 < NITER) load_stage(kc + 1);

#pragma unroll
        for (int s = 0; s < 4; s++) {
            float4 fa0 = sA[(s * 8 + wm * 2 + 0) * 32 + lane];
            float4 fa1 = sA[(s * 8 + wm * 2 + 1) * 32 + lane];
            float4 fb[4];
#pragma unroll
            for (int p = 0; p < 4; p++)
                fb[p] = sB[(s * 8 + wn * 4 + p) * 32 + lane];
#pragma unroll
            for (int nt = 0; nt < 8; nt++) {
                int p = nt >> 1;
                uint32_t b0 = (nt & 1) ? __float_as_uint(fb[p].z)
                                       : __float_as_uint(fb[p].x);
                uint32_t b1 = (nt & 1) ? __float_as_uint(fb[p].w)
                                       : __float_as_uint(fb[p].y);
                mma_tf32(acc[0][nt], fa0, b0, b1);
                mma_tf32(acc[1][nt], fa1, b0, b1);
            }
        }
    }

    // ---- epilogue: scale by routing weight, write per-slot scratch ----
    int r = lane >> 2, cq = (lane & 3) * 2;
#pragma unroll
    for (int mt = 0; mt < 2; mt++) {
#pragma unroll
        for (int rr = 0; rr < 2; rr++) {
            int mloc = wm * 32 + mt * 16 + r + rr * 8;
            if (mloc >= rows) continue;
            int   pack = s_pack[mloc];
            int   slot = ((uint32_t)pack) >> 31;
            int   tok  = pack & 0x7fffffff;
            float wt   = s_w[mloc];
            float* dst = g_scr + ((size_t)slot * BB + tok) * HH
                       + n0 + wn * 64 + cq;
#pragma unroll
            for (int nt = 0; nt < 8; nt++) {
                float2 v;
                v.x = wt * acc[mt][nt][rr * 2 + 0];
                v.y = wt * acc[mt][nt][rr * 2 + 1];
                *reinterpret_cast<float2*>(dst + nt * 8) = v;
            }
        }
    }
}

// ---------------------------------------------------------------------------
// Kernel 3: combine the two slots -> final output
// ---------------------------------------------------------------------------
__global__ void __launch_bounds__(256) combine_kernel(float4* __restrict__ out) {
    size_t i = (size_t)blockIdx.x * blockDim.x + threadIdx.x;
    const float4* s0 = reinterpret_cast<const float4*>(g_scr);
    const float4* s1 = reinterpret_cast<const float4*>(g_scr + (size_t)BB * HH);
    float4 a = s0[i], b = s1[i];
    out[i] = make_float4(a.x + b.x, a.y + b.y, a.z + b.z, a.w + b.w);
}

// ---------------------------------------------------------------------------
extern "C" void kernel_launch(void* const* d_in, const int* in_sizes, int n_in,
                              void* d_out, int out_size) {
    const float* x  = (const float*)d_in[0];   // [8192, 1024]
    const float* gw = (const float*)d_in[1];   // [1024, 8]
    const float* ew = (const float*)d_in[2];   // [8, 1024, 1024]
    float* out = (float*)d_out;                // [8192, 1024]

    zero_cnt_kernel<<<1, 32>>>();
    route_kernel<<<BB / 8, 256>>>(x, gw);
    moe_gemm_kernel<<<dim3(HH / BN, BB / BM, EE), 256>>>(x, ew);
    combine_kernel<<<(BB * HH / 4) / 256, 256>>>((float4*)out);
}

// round 4
// speedup vs baseline: 1.7851x; 1.7851x over previous
#include <cuda_runtime.h>
#include <cstdint>

// Problem dims
#define BB 8192
#define HH 1024
#define EE 8

// GEMM tile
#define BM 128
#define BN 128
#define BK 32
#define NITER (HH / BK)   // 32
#define ST 4              // cp.async pipeline stages

// smem: per stage A (128 rows x 128B) + B (32 rows x 512B) = 32KB
#define STAGE_FLOATS 8192
#define SMEM_GEMM_BYTES (ST * STAGE_FLOATS * 4 + BM * 8)   // +s_pack/s_w

// ---------------------------------------------------------------------------
// Device scratch (no allocation allowed anywhere)
// ---------------------------------------------------------------------------
__device__ int   g_cnt[EE];
__device__ int   g_tok[EE * BB];            // packed: tok | (slot << 31)
__device__ float g_wt [EE * BB];
__device__ float g_scr[2u * BB * HH];       // 64 MB: per-slot expert outputs
__device__ float g_xc [(size_t)BB * HH];    // 32 MB: tf32-rounded x
__device__ float g_ewc[(size_t)EE * HH * HH]; // 32 MB: tf32-rounded weights

// ---------------------------------------------------------------------------
__device__ __forceinline__ float f2tf32f(float f) {
    uint32_t r;
    asm("cvt.rna.tf32.f32 %0, %1;" : "=r"(r) : "f"(f));
    return __uint_as_float(r);
}

__device__ __forceinline__ void mma_tf32(float* c, const float* a,
                                         float b0, float b1) {
    asm volatile(
        "mma.sync.aligned.m16n8k8.row.col.f32.tf32.tf32.f32 "
        "{%0,%1,%2,%3}, {%4,%5,%6,%7}, {%8,%9}, {%0,%1,%2,%3};"
        : "+f"(c[0]), "+f"(c[1]), "+f"(c[2]), "+f"(c[3])
        : "r"(__float_as_uint(a[0])), "r"(__float_as_uint(a[1])),
          "r"(__float_as_uint(a[2])), "r"(__float_as_uint(a[3])),
          "r"(__float_as_uint(b0)), "r"(__float_as_uint(b1)));
}

__device__ __forceinline__ void cp16(uint32_t dst, const void* src) {
    asm volatile("cp.async.cg.shared.global [%0], [%1], 16;"
                 :: "r"(dst), "l"(src) : "memory");
}
#define CP_COMMIT() asm volatile("cp.async.commit_group;" ::: "memory")
#define CP_WAIT2()  asm volatile("cp.async.wait_group 2;" ::: "memory")

__device__ __forceinline__ uint32_t smem_u32(const void* p) {
    uint32_t a;
    asm("{ .reg .u64 t; cvta.to.shared.u64 t, %1; cvt.u32.u64 %0, t; }"
        : "=r"(a) : "l"(p));
    return a;
}

// ---------------------------------------------------------------------------
// Kernel 0: zero routing counters
// ---------------------------------------------------------------------------
__global__ void zero_cnt_kernel() {
    if (threadIdx.x < EE) g_cnt[threadIdx.x] = 0;
}

// ---------------------------------------------------------------------------
// Kernel 1: routing — one warp per token. Exact fp32 logits, top-2 with
// first-occurrence tie-break (matches jax.lax.top_k), softmax over the 2.
// Also emits the tf32-rounded copy of x (fused: x is already being read).
// ---------------------------------------------------------------------------
__global__ void __launch_bounds__(256) route_kernel(
    const float* __restrict__ x, const float* __restrict__ gw) {
    int tok = (blockIdx.x * blockDim.x + threadIdx.x) >> 5;
    int lid = threadIdx.x & 31;
    if (tok >= BB) return;

    const float* xr = x + (size_t)tok * HH;
    float*       xc = g_xc + (size_t)tok * HH;
    float acc[EE];
#pragma unroll
    for (int e = 0; e < EE; e++) acc[e] = 0.f;

    for (int i = lid; i < HH; i += 32) {
        float xv = xr[i];
        xc[i] = f2tf32f(xv);
        const float4* g = reinterpret_cast<const float4*>(gw + (size_t)i * EE);
        float4 g0 = g[0], g1 = g[1];
        acc[0] += xv * g0.x; acc[1] += xv * g0.y;
        acc[2] += xv * g0.z; acc[3] += xv * g0.w;
        acc[4] += xv * g1.x; acc[5] += xv * g1.y;
        acc[6] += xv * g1.z; acc[7] += xv * g1.w;
    }
#pragma unroll
    for (int off = 16; off > 0; off >>= 1)
#pragma unroll
        for (int e = 0; e < EE; e++)
            acc[e] += __shfl_xor_sync(0xffffffffu, acc[e], off);

    if (lid == 0) {
        int i0 = 0; float v0 = acc[0];
#pragma unroll
        for (int e = 1; e < EE; e++)
            if (acc[e] > v0) { v0 = acc[e]; i0 = e; }
        int i1 = -1; float v1 = -3.4e38f;
#pragma unroll
        for (int e = 0; e < EE; e++)
            if (e != i0 && acc[e] > v1) { v1 = acc[e]; i1 = e; }
        float ex1 = expf(v1 - v0);
        float inv = 1.0f / (1.0f + ex1);
        int p0 = atomicAdd(&g_cnt[i0], 1);
        g_tok[i0 * BB + p0] = tok;                    // slot 0
        g_wt [i0 * BB + p0] = inv;
        int p1 = atomicAdd(&g_cnt[i1], 1);
        g_tok[i1 * BB + p1] = tok | (int)0x80000000;  // slot 1
        g_wt [i1 * BB + p1] = ex1 * inv;
    }
}

// ---------------------------------------------------------------------------
// Kernel 1b: tf32-round the expert weights (one pass, reused 16x by GEMM)
// ---------------------------------------------------------------------------
__global__ void __launch_bounds__(256) cvt_w_kernel(const float4* __restrict__ src) {
    size_t i = (size_t)blockIdx.x * blockDim.x + threadIdx.x;
    float4 v = src[i];
    float4 o = make_float4(f2tf32f(v.x), f2tf32f(v.y),
                           f2tf32f(v.z), f2tf32f(v.w));
    reinterpret_cast<float4*>(g_ewc)[i] = o;
}

// ---------------------------------------------------------------------------
// Kernel 2: grouped expert GEMM. 128x128x32 tile, 256 thr (8 warps, 4x2),
// warp tile 32x64, mma.sync m16n8k8 tf32. cp.async 4-stage pipeline into
// XOR-swizzled natural-layout smem; conflict-free LDS.32 fragment loads.
// Inputs are pre-rounded to tf32 (g_xc / g_ewc referenced DIRECTLY as
// device globals — passing them as host-side args was the R3 bug).
//   A smem: [row 0..127][128B], granule (16B) index g -> g ^ (row&7)
//   B smem: [k 0..31][512B],    granule index g -> g ^ ((k&3)<<1)
// Epilogue scales by routing weight, STG to per-slot scratch (no atomics).
// ---------------------------------------------------------------------------
__global__ void __launch_bounds__(256, 1)
moe_gemm_kernel() {
    const float* __restrict__ xc  = g_xc;
    const float* __restrict__ ewc = g_ewc;

    int e   = blockIdx.z;
    int cnt = g_cnt[e];
    int m0  = blockIdx.y * BM;
    if (m0 >= cnt) return;
    int rows = min(BM, cnt - m0);
    int n0   = blockIdx.x * BN;

    extern __shared__ float smf[];
    uint32_t sbase = smem_u32(smf);
    int* s_pack = reinterpret_cast<int*>(smf + ST * STAGE_FLOATS);
    float* s_w  = reinterpret_cast<float*>(s_pack + BM);

    int tid  = threadIdx.x;
    int lane = tid & 31;
    int w    = tid >> 5;
    int wm   = w >> 1;      // 0..3 (M)
    int wn   = w & 1;       // 0..1 (N)

    if (tid < BM) {
        int idx = m0 + tid;
        if (idx < cnt) {
            s_pack[tid] = g_tok[e * BB + idx];
            s_w[tid]    = g_wt [e * BB + idx];
        } else {
            s_pack[tid] = 0;
            s_w[tid]    = 0.f;
        }
    }
    __syncthreads();

    // ---- producer address setup ----
    // A: thread t covers rows {p*32 + t>>3}, granule g = t&7 (16B)
    const float* asrc[4];
    uint32_t     adst[4];
    {
        int g = tid & 7, lr = tid >> 3;
#pragma unroll
        for (int p = 0; p < 4; p++) {
            int row = p * 32 + lr;
            int tk  = s_pack[row] & 0x7fffffff;
            asrc[p] = xc + (size_t)tk * HH + g * 4;
            adst[p] = (uint32_t)(row * 128 + ((g ^ (lr & 7)) << 4));
        }
    }
    // B: thread t covers rows k = {p*8 + t>>5}, granule g = t&31
    const float* bsrc[4];
    uint32_t     bdst[4];
    {
        int gB = tid & 31, k0 = tid >> 5;
#pragma unroll
        for (int p = 0; p < 4; p++) {
            int k = p * 8 + k0;
            bsrc[p] = ewc + (size_t)e * HH * HH + (size_t)k * HH + n0 + gB * 4;
            bdst[p] = (uint32_t)(16384 + k * 512 + ((gB ^ ((k0 & 3) << 1)) << 4));
        }
    }

    auto produce = [&](int kc) {
        uint32_t sb = sbase + (uint32_t)(kc & (ST - 1)) * (STAGE_FLOATS * 4);
#pragma unroll
        for (int p = 0; p < 4; p++) cp16(sb + adst[p], asrc[p] + kc * BK);
#pragma unroll
        for (int p = 0; p < 4; p++)
            cp16(sb + bdst[p], bsrc[p] + (size_t)kc * BK * HH);
        CP_COMMIT();
    };

    // ---- consumer fragment offsets (floats) ----
    int r = lane >> 2, c = lane & 3;
    int fa0 = wm * 1024 + r * 32 + c;       // A: row*(32f) + within-granule
    int fb0 = c * 128 + (r & 3);            // B: k*(128f) + (n&3)
    int offnt[8];
#pragma unroll
    for (int nt = 0; nt < 8; nt++)
        offnt[nt] = ((wn * 16 + nt * 2 + (r >> 2)) ^ (2 * c)) << 2;
    int axor[4][2];
#pragma unroll
    for (int s = 0; s < 4; s++) {
        axor[s][0] = ((2 * s)     ^ r) << 2;
        axor[s][1] = ((2 * s + 1) ^ r) << 2;
    }

    float acc[2][8][4];
#pragma unroll
    for (int mt = 0; mt < 2; mt++)
#pragma unroll
        for (int nt = 0; nt < 8; nt++)
#pragma unroll
            for (int q = 0; q < 4; q++) acc[mt][nt][q] = 0.f;

    produce(0); produce(1); produce(2);

    for (int kc = 0; kc < NITER; kc++) {
        CP_WAIT2();
        __syncthreads();
        if (kc + (ST - 1) < NITER) produce(kc + (ST - 1));

        const float* As = smf + (kc & (ST - 1)) * STAGE_FLOATS;
        const float* Bs = As + 4096;
#pragma unroll
        for (int s = 0; s < 4; s++) {
            float a[2][4];
#pragma unroll
            for (int mt = 0; mt < 2; mt++) {
                a[mt][0] = As[fa0 + mt * 512 +       axor[s][0]];
                a[mt][1] = As[fa0 + mt * 512 + 256 + axor[s][0]];
                a[mt][2] = As[fa0 + mt * 512 +       axor[s][1]];
                a[mt][3] = As[fa0 + mt * 512 + 256 + axor[s][1]];
            }
#pragma unroll
            for (int nt = 0; nt < 8; nt++) {
                float b0 = Bs[fb0 + s * 1024 +       offnt[nt]];
                float b1 = Bs[fb0 + s * 1024 + 512 + offnt[nt]];
                mma_tf32(acc[0][nt], a[0], b0, b1);
                mma_tf32(acc[1][nt], a[1], b0, b1);
            }
        }
    }

    // ---- epilogue: scale by routing weight, write per-slot scratch ----
    int cq = c * 2;
#pragma unroll
    for (int mt = 0; mt < 2; mt++) {
#pragma unroll
        for (int rr = 0; rr < 2; rr++) {
            int mloc = wm * 32 + mt * 16 + r + rr * 8;
            if (mloc >= rows) continue;
            int   pack = s_pack[mloc];
            int   slot = ((uint32_t)pack) >> 31;
            int   tk   = pack & 0x7fffffff;
            float wt   = s_w[mloc];
            float* dst = g_scr + ((size_t)slot * BB + tk) * HH
                       + n0 + wn * 64 + cq;
#pragma unroll
            for (int nt = 0; nt < 8; nt++) {
                float2 v;
                v.x = wt * acc[mt][nt][rr * 2 + 0];
                v.y = wt * acc[mt][nt][rr * 2 + 1];
                *reinterpret_cast<float2*>(dst + nt * 8) = v;
            }
        }
    }
}

// ---------------------------------------------------------------------------
// Kernel 3: combine the two slots -> final output
// ---------------------------------------------------------------------------
__global__ void __launch_bounds__(256) combine_kernel(float4* __restrict__ out) {
    size_t i = (size_t)blockIdx.x * blockDim.x + threadIdx.x;
    const float4* s0 = reinterpret_cast<const float4*>(g_scr);
    const float4* s1 = reinterpret_cast<const float4*>(g_scr + (size_t)BB * HH);
    float4 a = s0[i], b = s1[i];
    out[i] = make_float4(a.x + b.x, a.y + b.y, a.z + b.z, a.w + b.w);
}

// ---------------------------------------------------------------------------
extern "C" void kernel_launch(void* const* d_in, const int* in_sizes, int n_in,
                              void* d_out, int out_size) {
    const float* x  = (const float*)d_in[0];   // [8192, 1024]
    const float* gw = (const float*)d_in[1];   // [1024, 8]
    const float* ew = (const float*)d_in[2];   // [8, 1024, 1024]
    float* out = (float*)d_out;                // [8192, 1024]

    cudaFuncSetAttribute(moe_gemm_kernel,
                         cudaFuncAttributeMaxDynamicSharedMemorySize,
                         SMEM_GEMM_BYTES);

    zero_cnt_kernel<<<1, 32>>>();
    route_kernel<<<BB / 8, 256>>>(x, gw);
    cvt_w_kernel<<<(EE * HH * HH / 4) / 256, 256>>>((const float4*)ew);
    moe_gemm_kernel<<<dim3(HH / BN, BB / BM, EE), 256, SMEM_GEMM_BYTES>>>();
    combine_kernel<<<(BB * HH / 4) / 256, 256>>>((float4*)out);
}

// round 5
// speedup vs baseline: 1.8368x; 1.0289x over previous
#include <cuda_runtime.h>
#include <cstdint>

// Problem dims
#define BB 8192
#define HH 1024
#define EE 8

// GEMM tile: 128x256x32, 256 threads, 8 warps (4 M x 2 N), warp tile 32x128
#define BM 128
#define BN 256
#define BK 32
#define NITER (HH / BK)   // 32
#define ST 4              // cp.async pipeline stages

// per stage: A 128x128B (4096 f) + B 32x1024B (8192 f) = 48KB
#define STAGE_FLOATS 12288
#define SMEM_GEMM_BYTES (ST * STAGE_FLOATS * 4 + BM * 8)   // 197632

// ---------------------------------------------------------------------------
// Device scratch (no allocation allowed anywhere)
// ---------------------------------------------------------------------------
__device__ int   g_cnt[EE];
__device__ int   g_tok[EE * BB];            // packed: tok | (slot << 31)
__device__ float g_wt [EE * BB];
__device__ float g_scr[2u * BB * HH];       // 64 MB: per-slot expert outputs
__device__ float g_xc [(size_t)BB * HH];    // 32 MB: tf32-rounded x
__device__ float g_ewc[(size_t)EE * HH * HH]; // 32 MB: tf32-rounded weights

// ---------------------------------------------------------------------------
__device__ __forceinline__ float f2tf32f(float f) {
    uint32_t r;
    asm("cvt.rna.tf32.f32 %0, %1;" : "=r"(r) : "f"(f));
    return __uint_as_float(r);
}

__device__ __forceinline__ void mma_tf32(float* c, const float* a,
                                         float b0, float b1) {
    asm volatile(
        "mma.sync.aligned.m16n8k8.row.col.f32.tf32.tf32.f32 "
        "{%0,%1,%2,%3}, {%4,%5,%6,%7}, {%8,%9}, {%0,%1,%2,%3};"
        : "+f"(c[0]), "+f"(c[1]), "+f"(c[2]), "+f"(c[3])
        : "r"(__float_as_uint(a[0])), "r"(__float_as_uint(a[1])),
          "r"(__float_as_uint(a[2])), "r"(__float_as_uint(a[3])),
          "r"(__float_as_uint(b0)), "r"(__float_as_uint(b1)));
}

__device__ __forceinline__ void cp16(uint32_t dst, const void* src) {
    asm volatile("cp.async.cg.shared.global [%0], [%1], 16;"
                 :: "r"(dst), "l"(src) : "memory");
}
#define CP_COMMIT() asm volatile("cp.async.commit_group;" ::: "memory")
#define CP_WAIT2()  asm volatile("cp.async.wait_group 2;" ::: "memory")

__device__ __forceinline__ uint32_t smem_u32(const void* p) {
    uint32_t a;
    asm("{ .reg .u64 t; cvta.to.shared.u64 t, %1; cvt.u32.u64 %0, t; }"
        : "=r"(a) : "l"(p));
    return a;
}

// ---------------------------------------------------------------------------
// Kernel 0: zero routing counters
// ---------------------------------------------------------------------------
__global__ void zero_cnt_kernel() {
    if (threadIdx.x < EE) g_cnt[threadIdx.x] = 0;
}

// ---------------------------------------------------------------------------
// Kernel 1: routing — one warp per token. Exact fp32 logits, top-2 with
// first-occurrence tie-break (matches jax.lax.top_k), softmax over the 2.
// Also emits the tf32-rounded copy of x (fused: x is already being read).
// ---------------------------------------------------------------------------
__global__ void __launch_bounds__(256) route_kernel(
    const float* __restrict__ x, const float* __restrict__ gw) {
    int tok = (blockIdx.x * blockDim.x + threadIdx.x) >> 5;
    int lid = threadIdx.x & 31;
    if (tok >= BB) return;

    const float* xr = x + (size_t)tok * HH;
    float*       xc = g_xc + (size_t)tok * HH;
    float acc[EE];
#pragma unroll
    for (int e = 0; e < EE; e++) acc[e] = 0.f;

    for (int i = lid; i < HH; i += 32) {
        float xv = xr[i];
        xc[i] = f2tf32f(xv);
        const float4* g = reinterpret_cast<const float4*>(gw + (size_t)i * EE);
        float4 g0 = g[0], g1 = g[1];
        acc[0] += xv * g0.x; acc[1] += xv * g0.y;
        acc[2] += xv * g0.z; acc[3] += xv * g0.w;
        acc[4] += xv * g1.x; acc[5] += xv * g1.y;
        acc[6] += xv * g1.z; acc[7] += xv * g1.w;
    }
#pragma unroll
    for (int off = 16; off > 0; off >>= 1)
#pragma unroll
        for (int e = 0; e < EE; e++)
            acc[e] += __shfl_xor_sync(0xffffffffu, acc[e], off);

    if (lid == 0) {
        int i0 = 0; float v0 = acc[0];
#pragma unroll
        for (int e = 1; e < EE; e++)
            if (acc[e] > v0) { v0 = acc[e]; i0 = e; }
        int i1 = -1; float v1 = -3.4e38f;
#pragma unroll
        for (int e = 0; e < EE; e++)
            if (e != i0 && acc[e] > v1) { v1 = acc[e]; i1 = e; }
        float ex1 = expf(v1 - v0);
        float inv = 1.0f / (1.0f + ex1);
        int p0 = atomicAdd(&g_cnt[i0], 1);
        g_tok[i0 * BB + p0] = tok;                    // slot 0
        g_wt [i0 * BB + p0] = inv;
        int p1 = atomicAdd(&g_cnt[i1], 1);
        g_tok[i1 * BB + p1] = tok | (int)0x80000000;  // slot 1
        g_wt [i1 * BB + p1] = ex1 * inv;
    }
}

// ---------------------------------------------------------------------------
// Kernel 1b: tf32-round the expert weights (one pass, reused by GEMM)
// ---------------------------------------------------------------------------
__global__ void __launch_bounds__(256) cvt_w_kernel(const float4* __restrict__ src) {
    size_t i = (size_t)blockIdx.x * blockDim.x + threadIdx.x;
    float4 v = src[i];
    float4 o = make_float4(f2tf32f(v.x), f2tf32f(v.y),
                           f2tf32f(v.z), f2tf32f(v.w));
    reinterpret_cast<float4*>(g_ewc)[i] = o;
}

// ---------------------------------------------------------------------------
// Kernel 2: grouped expert GEMM. 128x256x32 tile, 256 thr, 8 warps (4x2),
// warp tile 32x128 -> 32 back-to-back MMAs per A-fragment load so the
// tensor pipe stays fed with only 2 warps/SMSP. cp.async 4-stage pipeline,
// XOR-swizzled natural-layout smem (conflict-free LDS.32 verified):
//   A smem: [row 0..127][128B], granule g -> g ^ (row&7)
//   B smem: [k 0..31][1024B],   granule g -> g ^ ((k&3)<<1)  (bits1-2 only)
// Inputs pre-rounded to tf32 (g_xc / g_ewc device globals referenced
// directly — never passed from host). Epilogue: scale by routing weight,
// plain STG to per-slot scratch (no atomics).
// ---------------------------------------------------------------------------
__global__ void __launch_bounds__(256, 1)
moe_gemm_kernel() {
    const float* __restrict__ xc  = g_xc;
    const float* __restrict__ ewc = g_ewc;

    int e   = blockIdx.z;
    int cnt = g_cnt[e];
    int m0  = blockIdx.y * BM;
    if (m0 >= cnt) return;
    int rows = min(BM, cnt - m0);
    int n0   = blockIdx.x * BN;

    extern __shared__ float smf[];
    uint32_t sbase = smem_u32(smf);
    int* s_pack = reinterpret_cast<int*>(smf + ST * STAGE_FLOATS);
    float* s_w  = reinterpret_cast<float*>(s_pack + BM);

    int tid  = threadIdx.x;
    int lane = tid & 31;
    int w    = tid >> 5;
    int wm   = w >> 1;      // 0..3 (M)
    int wn   = w & 1;       // 0..1 (N)

    if (tid < BM) {
        int idx = m0 + tid;
        if (idx < cnt) {
            s_pack[tid] = g_tok[e * BB + idx];
            s_w[tid]    = g_wt [e * BB + idx];
        } else {
            s_pack[tid] = 0;
            s_w[tid]    = 0.f;
        }
    }
    __syncthreads();

    // ---- producer address setup ----
    // A: thread t covers rows {p*32 + t>>3}, granule g = t&7 (16B)
    const float* asrc[4];
    uint32_t     adst[4];
    {
        int g = tid & 7, lr = tid >> 3;
#pragma unroll
        for (int p = 0; p < 4; p++) {
            int row = p * 32 + lr;
            int tk  = s_pack[row] & 0x7fffffff;
            asrc[p] = xc + (size_t)tk * HH + g * 4;
            adst[p] = (uint32_t)(row * 128 + ((g ^ (lr & 7)) << 4));
        }
    }
    // B: thread t covers k rows {p*8 + t>>5}, granules {t&31, (t&31)+32}.
    // Swizzle XOR touches only bits 1-2, so the +32 half keeps +512B both
    // in gmem (same row) and smem.
    const float* bsrc[4];
    uint32_t     bdst[4];
    {
        int gB = tid & 31, k0 = tid >> 5;
#pragma unroll
        for (int p = 0; p < 4; p++) {
            int k = p * 8 + k0;
            bsrc[p] = ewc + (size_t)e * HH * HH + (size_t)k * HH + n0 + gB * 4;
            bdst[p] = (uint32_t)(16384 + k * 1024 + ((gB ^ ((k0 & 3) << 1)) << 4));
        }
    }

    auto produce = [&](int kc) {
        uint32_t sb = sbase + (uint32_t)(kc & (ST - 1)) * (STAGE_FLOATS * 4);
#pragma unroll
        for (int p = 0; p < 4; p++) cp16(sb + adst[p], asrc[p] + kc * BK);
#pragma unroll
        for (int p = 0; p < 4; p++) {
            const float* s = bsrc[p] + (size_t)kc * BK * HH;
            cp16(sb + bdst[p], s);
            cp16(sb + bdst[p] + 512, s + 128);
        }
        CP_COMMIT();
    };

    // ---- consumer fragment offsets (floats) ----
    int r = lane >> 2, c = lane & 3;
    int fa0 = wm * 1024 + r * 32 + c;       // A: row*(32f) + within-granule
    int fb0 = c * 256 + (r & 3);            // B: k*(256f) + (n&3)
    int offnt[16];
#pragma unroll
    for (int nt = 0; nt < 16; nt++)
        offnt[nt] = ((wn * 32 + nt * 2 + (r >> 2)) ^ (2 * c)) << 2;
    int axor[4][2];
#pragma unroll
    for (int s = 0; s < 4; s++) {
        axor[s][0] = ((2 * s)     ^ r) << 2;
        axor[s][1] = ((2 * s + 1) ^ r) << 2;
    }

    float acc[2][16][4];
#pragma unroll
    for (int mt = 0; mt < 2; mt++)
#pragma unroll
        for (int nt = 0; nt < 16; nt++)
#pragma unroll
            for (int q = 0; q < 4; q++) acc[mt][nt][q] = 0.f;

    produce(0); produce(1); produce(2);

    for (int kc = 0; kc < NITER; kc++) {
        CP_WAIT2();
        __syncthreads();
        if (kc + (ST - 1) < NITER) produce(kc + (ST - 1));

        const float* As = smf + (kc & (ST - 1)) * STAGE_FLOATS;
        const float* Bs = As + 4096;
#pragma unroll
        for (int s = 0; s < 4; s++) {
            float a[2][4];
#pragma unroll
            for (int mt = 0; mt < 2; mt++) {
                a[mt][0] = As[fa0 + mt * 512 +       axor[s][0]];
                a[mt][1] = As[fa0 + mt * 512 + 256 + axor[s][0]];
                a[mt][2] = As[fa0 + mt * 512 +       axor[s][1]];
                a[mt][3] = As[fa0 + mt * 512 + 256 + axor[s][1]];
            }
            const float* Bk = Bs + fb0 + s * 2048;  // +8 k-rows per s
#pragma unroll
            for (int nt = 0; nt < 16; nt++) {
                float b0 = Bk[offnt[nt]];
                float b1 = Bk[offnt[nt] + 1024];    // +4 k-rows
                mma_tf32(acc[0][nt], a[0], b0, b1);
                mma_tf32(acc[1][nt], a[1], b0, b1);
            }
        }
    }

    // ---- epilogue: scale by routing weight, write per-slot scratch ----
    int cq = c * 2;
#pragma unroll
    for (int mt = 0; mt < 2; mt++) {
#pragma unroll
        for (int rr = 0; rr < 2; rr++) {
            int mloc = wm * 32 + mt * 16 + r + rr * 8;
            if (mloc >= rows) continue;
            int   pack = s_pack[mloc];
            int   slot = ((uint32_t)pack) >> 31;
            int   tk   = pack & 0x7fffffff;
            float wt   = s_w[mloc];
            float* dst = g_scr + ((size_t)slot * BB + tk) * HH
                       + n0 + wn * 128 + cq;
#pragma unroll
            for (int nt = 0; nt < 16; nt++) {
                float2 v;
                v.x = wt * acc[mt][nt][rr * 2 + 0];
                v.y = wt * acc[mt][nt][rr * 2 + 1];
                *reinterpret_cast<float2*>(dst + nt * 8) = v;
            }
        }
    }
}

// ---------------------------------------------------------------------------
// Kernel 3: combine the two slots -> final output
// ---------------------------------------------------------------------------
__global__ void __launch_bounds__(256) combine_kernel(float4* __restrict__ out) {
    size_t i = (size_t)blockIdx.x * blockDim.x + threadIdx.x;
    const float4* s0 = reinterpret_cast<const float4*>(g_scr);
    const float4* s1 = reinterpret_cast<const float4*>(g_scr + (size_t)BB * HH);
    float4 a = s0[i], b = s1[i];
    out[i] = make_float4(a.x + b.x, a.y + b.y, a.z + b.z, a.w + b.w);
}

// ---------------------------------------------------------------------------
extern "C" void kernel_launch(void* const* d_in, const int* in_sizes, int n_in,
                              void* d_out, int out_size) {
    const float* x  = (const float*)d_in[0];   // [8192, 1024]
    const float* gw = (const float*)d_in[1];   // [1024, 8]
    const float* ew = (const float*)d_in[2];   // [8, 1024, 1024]
    float* out = (float*)d_out;                // [8192, 1024]

    cudaFuncSetAttribute(moe_gemm_kernel,
                         cudaFuncAttributeMaxDynamicSharedMemorySize,
                         SMEM_GEMM_BYTES);

    zero_cnt_kernel<<<1, 32>>>();
    route_kernel<<<BB / 8, 256>>>(x, gw);
    cvt_w_kernel<<<(EE * HH * HH / 4) / 256, 256>>>((const float4*)ew);
    moe_gemm_kernel<<<dim3(HH / BN, BB / BM, EE), 256, SMEM_GEMM_BYTES>>>();
    combine_kernel<<<(BB * HH / 4) / 256, 256>>>((float4*)out);
}